// round 5
// baseline (speedup 1.0000x reference)
#include <cuda_runtime.h>

// ---- geometry ----
// kz=5 : 64 images 256x256, out 252x252 ; 126 colgroups(x2), 18 chunks x R=14 rows
// kz=3 : 64 images 128x128, out 126x126 ; 63 colgroups(x2),  9 chunks x R=14 rows
#define T5_THREADS 145152      // 64*126*18
#define B5_BLOCKS 567          // exact: 145152/256
#define T3_THREADS 36288       // 64*63*9
#define B3_BLOCKS 142          // ceil(36288/256)
#define NBLOCKS (B5_BLOCKS + B3_BLOCKS)   // 709

__device__ double g_part[NBLOCKS];
__device__ int    g_count;

typedef unsigned long long u64;

__device__ __forceinline__ u64 pack2(float lo, float hi) {
    u64 r; asm("mov.b64 %0, {%1,%2};" : "=l"(r) : "f"(lo), "f"(hi)); return r;
}
__device__ __forceinline__ u64 fma2(u64 a, u64 b, u64 c) {
    u64 d; asm("fma.rn.f32x2 %0, %1, %2, %3;" : "=l"(d) : "l"(a), "l"(b), "l"(c)); return d;
}
__device__ __forceinline__ u64 add2(u64 a, u64 b) {
    u64 d; asm("add.rn.f32x2 %0, %1, %2;" : "=l"(d) : "l"(a), "l"(b)); return d;
}
__device__ __forceinline__ u64 mul2(u64 a, u64 b) {
    u64 d; asm("mul.rn.f32x2 %0, %1, %2;" : "=l"(d) : "l"(a), "l"(b)); return d;
}
__device__ __forceinline__ void unpack2(u64 v, float& lo, float& hi) {
    asm("mov.b64 {%0,%1}, %2;" : "=f"(lo), "=f"(hi) : "l"(v));
}

// Horizontal stats for ONE packed column pair (windows at x0, x0+1) from
// KZ+1 contiguous floats. Antisymmetric col weights, center skipped.
template<int KZ>
__device__ __forceinline__ void hstats1(const float* __restrict__ p,
                                        u64 two2, u64 neg12,
                                        u64& o0, u64& oc, u64& o2)
{
    float f[KZ + 1];
#pragma unroll
    for (int c = 0; c < KZ + 1; c += 2) {
        float2 v = *reinterpret_cast<const float2*>(p + c);
        f[c] = v.x; f[c + 1] = v.y;
    }
    u64 pk[KZ];
#pragma unroll
    for (int c = 0; c < KZ; c++) pk[c] = pack2(f[c], f[c + 1]);

    u64 s0 = add2(pk[0], pk[1]);
#pragma unroll
    for (int c = 2; c < KZ; c++) s0 = add2(s0, pk[c]);
    u64 s2 = mul2(pk[0], pk[0]);
#pragma unroll
    for (int c = 1; c < KZ; c++) s2 = fma2(pk[c], pk[c], s2);
    u64 sc;
    if (KZ == 3) {
        sc = fma2(neg12, pk[0], pk[2]);
    } else { // KZ==5 weights (-2,-1,0,1,2)
        u64 d1 = fma2(neg12, pk[1], pk[3]);
        u64 d2 = fma2(neg12, pk[0], pk[4]);
        sc = fma2(two2, d2, d1);
    }
    o0 = s0; oc = sc; o2 = s2;
}

// Per-thread: 2 output columns, R output rows. Register ring of KZ rows of stats.
template<int KZ, int R, int CG, int CH>
__device__ __forceinline__ float thread_work(const float* __restrict__ src0,
                                             int H, int W, int t)
{
    constexpr int PERIMG = CG * CH;
    const int img   = t / PERIMG;
    int rem         = t - img * PERIMG;
    const int chunk = rem / CG;
    const int cg    = rem - chunk * CG;
    const float* __restrict__ src = src0 + (size_t)img * H * W
                                  + (size_t)(chunk * R) * W + cg * 2;

    constexpr float ib = 1.f / (float)(KZ * KZ);
    constexpr float il = 12.f / (float)(KZ * KZ * (KZ * KZ - 1));
    const u64 two2   = pack2(2.f, 2.f);
    const u64 neg12  = pack2(-1.f, -1.f);
    const u64 negib2 = pack2(-ib, -ib);
    const u64 negil2 = pack2(-il, -il);

    u64 r0[KZ], rc[KZ], r2[KZ];
    u64 acc = 0ull;   // (0.f, 0.f)

    const float* p = src;
#pragma unroll
    for (int w = 0; w < KZ - 1; w++) {
        hstats1<KZ>(p, two2, neg12, r0[w], rc[w], r2[w]);
        p += W;
    }

#pragma unroll
    for (int i = 0; i < R; i++) {
        const int slot = (i + KZ - 1) % KZ;
        hstats1<KZ>(p, two2, neg12, r0[slot], rc[slot], r2[slot]);
        p += W;

        const int s0i = i % KZ, s1i = (i + 1) % KZ;
        u64 S0 = add2(r0[s0i], r0[s1i]);
        u64 S2 = add2(r2[s0i], r2[s1i]);
        u64 Sc = add2(rc[s0i], rc[s1i]);
#pragma unroll
        for (int a = 2; a < KZ; a++) {
            const int s = (i + a) % KZ;
            S0 = add2(S0, r0[s]);
            S2 = add2(S2, r2[s]);
            Sc = add2(Sc, rc[s]);
        }
        u64 Sr;
        if (KZ == 3) {
            Sr = fma2(neg12, r0[i % 3], r0[(i + 2) % 3]);
        } else {
            u64 d1 = fma2(neg12, r0[(i + 1) % 5], r0[(i + 3) % 5]);
            u64 d2 = fma2(neg12, r0[i % 5], r0[(i + 4) % 5]);
            Sr = fma2(two2, d2, d1);
        }
        u64 u = mul2(Sc, Sc);
        u     = fma2(Sr, Sr, u);
        u64 v = mul2(S0, S0);
        u64 q = fma2(v, negib2, S2);
        acc   = add2(acc, fma2(u, negil2, q));
    }
    float a0, a1;
    unpack2(acc, a0, a1);
    return a0 + a1;
}

__global__ void __launch_bounds__(256, 4) fused_kernel(const float* __restrict__ f0,
                                                       const float* __restrict__ f1,
                                                       float* __restrict__ out)
{
    const int tid = threadIdx.x;
    float acc = 0.f;
    double scale;

    if (blockIdx.x < B5_BLOCKS) {          // kz5 first: long poles start earliest
        const int t = blockIdx.x * 256 + tid;   // exact fit
        acc = thread_work<5, 14, 126, 18>(f1, 256, 256, t);
        scale = 1.0 / (32.0 * 252.0 * 252.0);
    } else {
        const int t = (blockIdx.x - B5_BLOCKS) * 256 + tid;
        if (t < T3_THREADS)
            acc = thread_work<3, 14, 63, 9>(f0, 128, 128, t);
        scale = 1.0 / (32.0 * 126.0 * 126.0);
    }

#pragma unroll
    for (int o = 16; o > 0; o >>= 1) acc += __shfl_down_sync(0xffffffffu, acc, o);
    __shared__ float wsum[8];
    __shared__ bool  lastflag;
    if ((tid & 31) == 0) wsum[tid >> 5] = acc;
    __syncthreads();
    if (tid < 32) {
        float v = (tid < 8) ? wsum[tid] : 0.f;
#pragma unroll
        for (int o = 4; o > 0; o >>= 1) v += __shfl_down_sync(0xffffffffu, v, o);
        if (tid == 0) {
            g_part[blockIdx.x] = (double)v * scale;
            __threadfence();
            int done = atomicAdd(&g_count, 1);
            lastflag = (done == NBLOCKS - 1);
        }
    }
    __syncthreads();

    if (lastflag) {
        __threadfence();
        double s = 0.0;
        for (int i = tid; i < NBLOCKS; i += 256) s += g_part[i];
#pragma unroll
        for (int o = 16; o > 0; o >>= 1) s += __shfl_down_sync(0xffffffffu, s, o);
        __shared__ double ws[8];
        if ((tid & 31) == 0) ws[tid >> 5] = s;
        __syncthreads();
        if (tid < 32) {
            double v = (tid < 8) ? ws[tid] : 0.0;
#pragma unroll
            for (int o = 4; o > 0; o >>= 1) v += __shfl_down_sync(0xffffffffu, v, o);
            if (tid == 0) { out[0] = (float)v; g_count = 0; }
        }
    }
}

extern "C" void kernel_launch(void* const* d_in, const int* in_sizes, int n_in,
                              void* d_out, int out_size)
{
    const float* flow0 = (const float*)d_in[0];  // (32,2,128,128)
    const float* flow1 = (const float*)d_in[1];  // (32,2,256,256)
    if (n_in >= 2 && in_sizes[0] > in_sizes[1]) {
        const float* t = flow0; flow0 = flow1; flow1 = t;
    }
    fused_kernel<<<NBLOCKS, 256>>>(flow0, flow1, (float*)d_out);
}